// round 17
// baseline (speedup 1.0000x reference)
#include <cuda_runtime.h>

// FastFood layer: out[n, :] = 1/32 * [cos(t), sin(t)] + bias,
//   t = (1/32) * S .* FWHT( G .* Perm( FWHT( B .* x ) ) )   per stack.
// D = 1024, STACK = 4, out row = 8192 floats.
//
// ONE WARP per (row, stack): 32 threads x 32 elements in registers.
// FWHT_1024 factored over bits {b0,b1,b7,b8,b9} (register butterfly, phase A)
// and {b2..b6} (register butterfly, phase B) with ONE smem exchange between.
// FWHT1 runs A->B (ending in smem for the random permutation gather);
// FWHT2 runs B->A (gather straight into phase-B regs, ends in phase-A regs
// -> epilogue needs no smem reads).
// Butterflies use packed f32x2 (add.rn.f32x2 / fma.rn.f32x2): each 5-bit
// radix-32 network = 1 scalar stage (pair-internal bit) + 4 packed stages,
// 96 ops instead of 160 scalar FADDs. fma(b,(-1,-1),a) == a-b exactly.
//
// Prep pass (16 blocks): Bb (B as sign bytes), P16p/Gp (gather params,
// phase-B packed, swizzle pre-applied), Ssc (S/32), g_bnz (bias-zero flags).

#define DD 1024
#define SSTACK 4
#define NE (SSTACK * DD)        // 4096

typedef unsigned long long ull;

__device__ __align__(16) short g_P16p[NE];
__device__ __align__(16) float g_Gp[NE];
__device__ __align__(16) float g_Ssc[NE];
__device__ __align__(16) unsigned char g_Bb[NE];
__device__ __align__(16) int g_bnz[16];

__device__ __forceinline__ int swz(int e) {
    return e ^ (((e >> 7) & 7) << 2);
}

// ---------- packed f32x2 helpers ----------
__device__ __forceinline__ ull pk(float lo, float hi) {
    ull d;
    asm("mov.b64 %0, {%1, %2};" : "=l"(d) : "f"(lo), "f"(hi));
    return d;
}
__device__ __forceinline__ void upk(ull p, float& lo, float& hi) {
    asm("mov.b64 {%0, %1}, %2;" : "=f"(lo), "=f"(hi) : "l"(p));
}
__device__ __forceinline__ ull add2(ull a, ull b) {
    ull d;
    asm("add.rn.f32x2 %0, %1, %2;" : "=l"(d) : "l"(a), "l"(b));
    return d;
}
__device__ __forceinline__ ull sub2(ull a, ull b) {   // exact a - b
    ull d;
    const ull n1 = 0xBF800000BF800000ULL;             // (-1.0f, -1.0f)
    asm("fma.rn.f32x2 %0, %1, %2, %3;" : "=l"(d) : "l"(b), "l"(n1), "l"(a));
    return d;
}

// radix-32 butterfly over the 5 register-index bits.
// Scalar stage on bit0 (pairs are adjacent v entries), 4 packed stages.
__device__ __forceinline__ void fwht32(float v[32]) {
    #pragma unroll
    for (int r = 0; r < 32; r += 2) {        // stage: reg bit0
        float a = v[r], b = v[r + 1];
        v[r] = a + b; v[r + 1] = a - b;
    }
    ull p[16];
    #pragma unroll
    for (int j = 0; j < 16; j++) p[j] = pk(v[2*j], v[2*j+1]);
    #pragma unroll
    for (int st = 1; st < 16; st <<= 1) {    // stages: reg bits 1..4, packed
        #pragma unroll
        for (int j = 0; j < 16; j++) {
            if (!(j & st)) {
                ull a = p[j], b = p[j | st];
                p[j]      = add2(a, b);
                p[j | st] = sub2(a, b);
            }
        }
    }
    #pragma unroll
    for (int j = 0; j < 16; j++) upk(p[j], v[2*j], v[2*j+1]);
}

__global__ __launch_bounds__(256)
void prep_kernel(const int*   __restrict__ P,
                 const float* __restrict__ S,
                 const float* __restrict__ B,
                 const float* __restrict__ G,
                 const float* __restrict__ bias)
{
    const int t = blockIdx.x * 256 + threadIdx.x;      // 0..4095
    g_Ssc[t] = S[t] * 0.03125f;
    g_Bb[t]  = (B[t] < 0.0f) ? 0x80u : 0x00u;

    // phase-B-packed gather params: t = sb + (cp<<6)|(l<<1)|par
    {
        const int sb  = (t >> 10) << 10;
        const int j   = t & 1023;
        const int cp  = j >> 6;
        const int l   = (j >> 1) & 31;
        const int par = j & 1;
        const int c   = (cp << 1) | par;
        const int ep  = ((l >> 2) << 7) | (c << 2) | (l & 3);   // phase-B element
        g_P16p[t] = (short)swz(P[sb + ep] - sb);
        g_Gp[t]   = G[sb + ep];
    }

    // distributed bias scan: block b checks bias[b*512 .. b*512+512)
    int nz = 0;
    const int base = blockIdx.x * 512 + threadIdx.x;
    nz |= (bias[base] != 0.0f);
    nz |= (bias[base + 256] != 0.0f);
    nz = __syncthreads_or(nz);
    if (threadIdx.x == 0) g_bnz[blockIdx.x] = nz;
}

__global__ __launch_bounds__(256, 3)
void fastfood_kernel(const float* __restrict__ x,
                     const float* __restrict__ bias,
                     float* __restrict__ out)
{
    __shared__ float buf[8][DD];
    const int l    = threadIdx.x & 31;          // lane
    const int wu   = threadIdx.x >> 5;          // warp (unit) in block
    const int unit = blockIdx.x * 8 + wu;       // global (row,stack)
    const int row  = unit >> 2;
    const int sb   = (unit & 3) << 10;
    float* hs = buf[wu];

    const int hi = l >> 2;                      // phase-B lane bits b9b8b7
    const int lo = l & 3;                       // phase-B lane bits b1b0

    // bias-nonzero flag (uniform; 4 broadcast loads)
    int bnz;
    {
        int4 f0 = *(const int4*)(g_bnz);
        int4 f1 = *(const int4*)(g_bnz + 4);
        int4 f2 = *(const int4*)(g_bnz + 8);
        int4 f3 = *(const int4*)(g_bnz + 12);
        bnz = f0.x | f0.y | f0.z | f0.w | f1.x | f1.y | f1.z | f1.w |
              f2.x | f2.y | f2.z | f2.w | f3.x | f3.y | f3.z | f3.w;
    }

    // phase-A: reg r=(i<<2)|m holds element e  = (i<<7) | (l<<2) | m
    // phase-B: reg c        holds element e' = (hi<<7) | (c<<2) | lo
    float v[32];

    // ================= FWHT #1  (A -> B, ends in smem) =================
    const float* xr = x + (size_t)row * DD;
    #pragma unroll
    for (int i = 0; i < 8; i++) {               // fused x*B, B = sign bytes
        float4   xv = *(const float4*)(xr + (i << 7) + (l << 2));
        unsigned bw = *(const unsigned*)(g_Bb + sb + (i << 7) + (l << 2));
        v[4*i+0] = __int_as_float(__float_as_int(xv.x) ^ (int)__byte_perm(bw, 0, 0x0444));
        v[4*i+1] = __int_as_float(__float_as_int(xv.y) ^ (int)__byte_perm(bw, 0, 0x1444));
        v[4*i+2] = __int_as_float(__float_as_int(xv.z) ^ (int)__byte_perm(bw, 0, 0x2444));
        v[4*i+3] = __int_as_float(__float_as_int(xv.w) ^ (int)__byte_perm(bw, 0, 0x3444));
    }
    fwht32(v);                                  // stages b0,b1,b7,b8,b9

    #pragma unroll
    for (int i = 0; i < 8; i++)                 // exchange write (STS.128)
        *(float4*)&hs[(i << 7) | ((l ^ i) << 2)] =
            make_float4(v[4*i], v[4*i+1], v[4*i+2], v[4*i+3]);
    __syncwarp();
    #pragma unroll
    for (int c = 0; c < 32; c++)                // exchange read (conflict-free)
        v[c] = hs[(hi << 7) | (((c ^ hi) & 31) << 2) | lo];
    fwht32(v);                                  // stages b2..b6  -> FWHT1 done

    #pragma unroll
    for (int c = 0; c < 32; c++)                // full result into smem (own slots)
        hs[(hi << 7) | (((c ^ hi) & 31) << 2) | lo] = v[c];
    __syncwarp();

    // ====== permutation gather * G straight into phase-B registers ======
    #pragma unroll
    for (int cp = 0; cp < 16; cp++) {
        short2 pv = *(const short2*)(g_P16p + sb + (cp << 6) + (l << 1));
        float2 gv = *(const float2*)(g_Gp   + sb + (cp << 6) + (l << 1));
        v[2*cp + 0] = hs[pv.x] * gv.x;
        v[2*cp + 1] = hs[pv.y] * gv.y;
    }
    __syncwarp();                               // gathers done before overwrite

    // ================= FWHT #2  (B -> A, ends in registers) =================
    fwht32(v);                                  // stages b2..b6
    #pragma unroll
    for (int c = 0; c < 32; c++)                // exchange write (conflict-free)
        hs[(hi << 7) | (((c ^ hi) & 31) << 2) | lo] = v[c];
    __syncwarp();
    #pragma unroll
    for (int i = 0; i < 8; i++) {               // exchange read (LDS.128)
        float4 h4 = *(const float4*)&hs[(i << 7) | ((l ^ i) << 2)];
        v[4*i+0] = h4.x; v[4*i+1] = h4.y; v[4*i+2] = h4.z; v[4*i+3] = h4.w;
    }
    fwht32(v);                                  // stages b0,b1,b7,b8,b9 -> done

    // ================= epilogue (registers only) =================
    const float c32 = 0.03125f;                 // sqrt(1/D)
    float* orow = out + (size_t)row * (2 * NE) + sb;
    if (!bnz) {
        #pragma unroll
        for (int i = 0; i < 8; i++) {
            float4 s4 = *(const float4*)(g_Ssc + sb + (i << 7) + (l << 2));
            float4 oc, os; float sn, cs;
            __sincosf(v[4*i+0] * s4.x, &sn, &cs); oc.x = c32 * cs; os.x = c32 * sn;
            __sincosf(v[4*i+1] * s4.y, &sn, &cs); oc.y = c32 * cs; os.y = c32 * sn;
            __sincosf(v[4*i+2] * s4.z, &sn, &cs); oc.z = c32 * cs; os.z = c32 * sn;
            __sincosf(v[4*i+3] * s4.w, &sn, &cs); oc.w = c32 * cs; os.w = c32 * sn;
            *(float4*)(orow + (i << 7) + (l << 2))      = oc;   // cos half
            *(float4*)(orow + NE + (i << 7) + (l << 2)) = os;   // sin half
        }
    } else {
        #pragma unroll
        for (int i = 0; i < 8; i++) {
            float4 s4  = *(const float4*)(g_Ssc + sb + (i << 7) + (l << 2));
            float4 bc4 = *(const float4*)(bias + sb + (i << 7) + (l << 2));
            float4 bs4 = *(const float4*)(bias + NE + sb + (i << 7) + (l << 2));
            float4 oc, os; float sn, cs;
            __sincosf(v[4*i+0] * s4.x, &sn, &cs); oc.x = c32*cs + bc4.x; os.x = c32*sn + bs4.x;
            __sincosf(v[4*i+1] * s4.y, &sn, &cs); oc.y = c32*cs + bc4.y; os.y = c32*sn + bs4.y;
            __sincosf(v[4*i+2] * s4.z, &sn, &cs); oc.z = c32*cs + bc4.z; os.z = c32*sn + bs4.z;
            __sincosf(v[4*i+3] * s4.w, &sn, &cs); oc.w = c32*cs + bc4.w; os.w = c32*sn + bs4.w;
            *(float4*)(orow + (i << 7) + (l << 2))      = oc;
            *(float4*)(orow + NE + (i << 7) + (l << 2)) = os;
        }
    }
}

extern "C" void kernel_launch(void* const* d_in, const int* in_sizes, int n_in,
                              void* d_out, int out_size) {
    // metadata order: x, B, G, S, bias, H (unused: FWHT replaces it), P
    const float* x    = (const float*)d_in[0];
    const float* B    = (const float*)d_in[1];
    const float* G    = (const float*)d_in[2];
    const float* S    = (const float*)d_in[3];
    const float* bias = (const float*)d_in[4];
    const int*   P    = (const int*)d_in[6];
    float* out = (float*)d_out;

    prep_kernel<<<16, 256>>>(P, S, B, G, bias);

    const int nrows = in_sizes[0] / DD;              // 8192
    const int nunits = nrows * SSTACK;               // 32768 (row,stack) units
    fastfood_kernel<<<nunits / 8, 256>>>(x, bias, out);
}